// round 15
// baseline (speedup 1.0000x reference)
#include <cuda_runtime.h>

typedef unsigned long long u64;

#define NQ     14
#define DIM    16384
#define NL     6
#define NG     (NL * NQ)
#define NTHR   256

// ---------------- packed f32x2 helpers (PTX-only on sm_103a) ----------------
__device__ __forceinline__ u64 pk2(float x, float y) {
    u64 r; asm("mov.b64 %0,{%1,%2};" : "=l"(r) : "f"(x), "f"(y)); return r;
}
__device__ __forceinline__ void upk2(u64 v, float& x, float& y) {
    asm("mov.b64 {%0,%1},%2;" : "=f"(x), "=f"(y) : "l"(v));
}
__device__ __forceinline__ u64 mul2(u64 a, u64 b) {
    u64 r; asm("mul.rn.f32x2 %0,%1,%2;" : "=l"(r) : "l"(a), "l"(b)); return r;
}
__device__ __forceinline__ u64 fma2(u64 a, u64 b, u64 c) {
    u64 r; asm("fma.rn.f32x2 %0,%1,%2,%3;" : "=l"(r) : "l"(a), "l"(b), "l"(c)); return r;
}
__device__ __forceinline__ u64 swap2(u64 a) {
    u64 r;
    asm("{\n\t.reg .f32 x,y;\n\tmov.b64 {x,y},%1;\n\tmov.b64 %0,{y,x};\n\t}"
        : "=l"(r) : "l"(a));
    return r;
}

// CNOT-ring permutation (GF(2)-linear): bits 0..12 = suffix-XOR, bit13 = XOR(0..12)
__device__ __forceinline__ unsigned Pfold(unsigned i) {
    unsigned z = i ^ (i >> 1);
    z ^= z >> 2; z ^= z >> 4; z ^= z >> 8;
    return (z & 0x1FFFu) | (((z ^ (i >> 13)) & 1u) << 13);
}
// float-word swizzle: XOR bits 1-5 with bits 6-10 (keeps bit0 -> u64 pairs intact)
__device__ __forceinline__ unsigned ssf(unsigned w) {
    return w ^ (((w >> 6) & 31u) << 1);
}

// Branch-free tan-form RX gate (always form A), state imag stored NEGATED:
//   r' = r - tau*i~p ; i~' = i~ + tau*rp    (4 fma2 per pair-op)
#define GATE_T(RM, T2, NT2)                                                 \
    _Pragma("unroll")                                                       \
    for (int k = 0; k < 32; ++k) {                                          \
        if (!(k & (RM))) {                                                  \
            const int k1 = k | (RM);                                        \
            u64 i0 = Ri[k], i1 = Ri[k1];                                    \
            Ri[k]  = fma2((T2),  Rr[k1], i0);                               \
            Ri[k1] = fma2((T2),  Rr[k],  i1);                               \
            Rr[k]  = fma2((NT2), i1, Rr[k]);                                \
            Rr[k1] = fma2((NT2), i0, Rr[k1]);                               \
        }                                                                   \
    }

__global__ void __launch_bounds__(NTHR, 1)
qlayer_kernel(const float* __restrict__ x,
              const float* __restrict__ params,
              float* __restrict__ out)
{
    extern __shared__ __align__(16) float sm[];
    float* sre = sm;            // DIM floats (real)
    float* sim = sm + DIM;      // DIM floats (negated imag)
    u64*   dre = (u64*)sre;     // packed pairs on i-bit0
    u64*   dim_ = (u64*)sim;

    __shared__ float gtau[NG];      // per-gate signed tau (form folded into sign)
    __shared__ float gdef[NG];      // per-gate deferred scalar (c or s)
    __shared__ unsigned gmsk;       // accumulated deferred-X mask
    __shared__ float gG2;           // squared product of deferred scalars
    __shared__ float red[NQ];

    const int b = blockIdx.x;
    const int t = threadIdx.x;      // 8 bits
    const int lane = t & 31;
    const int hiB  = t >> 5;        // 3 bits (warp id) = i bits 11-13 in passes A/B
    const int midB = t & 31;

    // stage 1: raw cos/sin of gate half-angles
    if (t < NG) {
        float h = 0.5f * params[t];
        gtau[t] = cosf(h);
        gdef[t] = sinf(h);
    }
    if (t == 0) gmsk = 0u;
    if (t < NQ) red[t] = 0.0f;
    __syncthreads();

    // stage 2: branch-free tan-form precompute.
    // form B (|s|>|c|): gate = s * (-iX) * (I + (-c/s) J); the (-iX) defers to a
    // final XOR mask, transformed by P once per remaining layer (incl. virtual last).
    if (t < NG) {
        float c = gtau[t], s = gdef[t];
        int fb = fabsf(s) > fabsf(c);
        gtau[t] = fb ? (-c / s) : (s / c);
        gdef[t] = fb ? s : c;
        if (fb) {
            const int l = t / NQ;
            const int q = t - l * NQ;
            unsigned m = 1u << (13 - q);       // i-bit of qubit q
            for (int n = 0; n < NL - l; ++n) m = Pfold(m);
            atomicXor(&gmsk, m);
        }
    }

    // ---------------- init product state directly into pass-A registers --------
    // pass-A layout: i = (t<<6) | (k<<1) | b0 ; bit bb of i <-> qubit (13-bb)
    // amp(i) = m(i) * (-i)^popcount(i) ; stored imag is NEGATED
    u64 Rr[32], Ri[32];
    {
        float cx[NQ], sx[NQ];
#pragma unroll
        for (int q = 0; q < NQ; ++q) {
            float h = 0.5f * x[b * NQ + q];
            cx[q] = cosf(h);
            sx[q] = sinf(h);
        }
        float hm = 1.0f;                    // t bit kk -> i bit 6+kk -> qubit 7-kk
#pragma unroll
        for (int kk = 0; kk < 8; ++kk)
            hm *= ((t >> kk) & 1) ? sx[7 - kk] : cx[7 - kk];
        const int hp = __popc((unsigned)t) & 3;
        const float wr = (hp == 0) ? 1.0f : ((hp == 2) ? -1.0f : 0.0f);
        const float wi = (hp == 3) ? 1.0f : ((hp == 1) ? -1.0f : 0.0f);
#pragma unroll
        for (int k = 0; k < 32; ++k) {
            float m5 = hm;                  // j = 2k ; j bit mm -> qubit 13-mm
#pragma unroll
            for (int mm = 1; mm < 6; ++mm)
                m5 *= (((2 * k) >> mm) & 1) ? sx[13 - mm] : cx[13 - mm];
            float m0 = m5 * cx[13];         // b0 = 0
            float m1 = m5 * sx[13];         // b0 = 1
            const int ck = __popc((unsigned)k) & 3;   // compile-time per k
            float wkr, wki;
            if      (ck == 0) { wkr =  wr; wki =  wi; }
            else if (ck == 1) { wkr =  wi; wki = -wr; }
            else if (ck == 2) { wkr = -wr; wki = -wi; }
            else              { wkr = -wi; wki =  wr; }
            // amp0 = m0*w ; amp1 = m1*w*(-i) ; store NEGATED imag
            Rr[k] = pk2( m0 * wkr,  m1 * wki);
            Ri[k] = pk2(-m0 * wki,  m1 * wkr);
        }
    }
    __syncthreads();

    // squared global deferred scale (thread 0; hidden under layer-0 passes A+B)
    if (t == 0) {
        float G = 1.0f;
#pragma unroll 1
        for (int g = 0; g < NG; ++g) G *= gdef[g];
        gG2 = G * G;
    }

    // pass-C thread base (i bits from lane/hiB): lane bits at i{3,4,6,7,10},
    // warp bits at i{5,8,9} -- verified conflict-free geometry
    const unsigned Cbase =
        ((unsigned)(lane & 1)        << 3)  |
        ((unsigned)((lane >> 1) & 1) << 4)  |
        ((unsigned)(hiB & 1)         << 5)  |
        ((unsigned)((lane >> 2) & 1) << 6)  |
        ((unsigned)((lane >> 3) & 1) << 7)  |
        ((unsigned)((hiB >> 1) & 1)  << 8)  |
        ((unsigned)((hiB >> 2) & 1)  << 9)  |
        ((unsigned)((lane >> 4) & 1) << 10);
    const unsigned hi5C   = (Cbase >> 6) & 31u;
    const unsigned dbaseC = (Cbase >> 1) ^ hi5C;   // u64-index base for pass C
    const unsigned pbC    = Pfold(Cbase);
    const unsigned spbC   = ssf(pbC);              // float-word store base (pass C)

#pragma unroll 1
    for (int l = 0; l < NL; ++l) {
        const float* lt = gtau + l * NQ;

        // ===== pass A : i = (t<<6)|(k<<1)|b0 ; gates on i bits 0..5 =====
        if (l > 0) {
#pragma unroll
            for (int k = 0; k < 32; ++k) {
                int du = t * 32 + (k ^ lane);
                Rr[k] = dre[du];
                Ri[k] = dim_[du];
            }
        }
        {   // gate on i bit0 (qubit 13): pack bit -> half swaps, tan form
            float tu = lt[13];
            u64 t2 = pk2(tu, tu), nt2 = pk2(-tu, -tu);
#pragma unroll
            for (int k = 0; k < 32; ++k) {
                u64 rs = swap2(Rr[k]);
                u64 is = swap2(Ri[k]);
                Rr[k] = fma2(nt2, is, Rr[k]);
                Ri[k] = fma2(t2,  rs, Ri[k]);
            }
        }
#pragma unroll
        for (int m = 1; m < 6; ++m) {        // i bit m -> qubit 13-m
            float tu = lt[13 - m];
            u64 t2 = pk2(tu, tu), nt2 = pk2(-tu, -tu);
            GATE_T(1 << (m - 1), t2, nt2)
        }
#pragma unroll
        for (int k = 0; k < 32; ++k) {
            int du = t * 32 + (k ^ lane);
            dre[du] = Rr[k];
            dim_[du] = Ri[k];
        }
        // A->B exchange is warp-local (d bits 10-12 = warp id on both sides):
        // warp-level sync suffices and lets warps' L1/FMA phases overlap.
        __syncwarp();

        // ===== pass B : u64 idx = (hiB<<10)|(k<<5)|(midB^k) ; gates on i bits 6..10
#pragma unroll
        for (int k = 0; k < 32; ++k) {
            int du = (hiB << 10) | (k << 5) | (midB ^ k);
            Rr[k] = dre[du];
            Ri[k] = dim_[du];
        }
#pragma unroll
        for (int m = 0; m < 5; ++m) {        // i bit 6+m -> qubit 7-m
            float tu = lt[7 - m];
            u64 t2 = pk2(tu, tu), nt2 = pk2(-tu, -tu);
            GATE_T(1 << m, t2, nt2)
        }
#pragma unroll
        for (int k = 0; k < 32; ++k) {
            int du = (hiB << 10) | (k << 5) | (midB ^ k);
            dre[du] = Rr[k];
            dim_[du] = Ri[k];
        }
        __syncthreads();                     // B -> C is cross-warp

        // ===== pass C : k bits{0,1}->i{1,2}, k bits{2,3,4}->i{11,12,13} =====
#pragma unroll
        for (int k = 0; k < 32; ++k) {
            unsigned du = dbaseC ^ ((unsigned)(k & 3) | ((unsigned)(k >> 2) << 10));
            Rr[k] = dre[du];
            Ri[k] = dim_[du];
        }
        if (l < NL - 1) {
            // SPLIT gather-guard: non-blocking arrival now; wait just before the
            // scatter. The 3 register-local gates below overlap the barrier drain.
            asm volatile("bar.arrive 1, %0;" :: "n"(2 * NTHR) : "memory");
        }
#pragma unroll
        for (int m = 0; m < 3; ++m) {        // i bit 11+m -> qubit 2-m
            float tu = lt[2 - m];
            u64 t2 = pk2(tu, tu), nt2 = pk2(-tu, -tu);
            GATE_T(1 << (2 + m), t2, nt2)
        }

        if (l < NL - 1) {
            // wait until ALL threads' gathers have arrived (256 arrive + 256 sync
            // = 512 total) -- only then is the scatter WAR-safe.
            asm volatile("bar.sync 1, %0;" :: "n"(2 * NTHR) : "memory");
            // CNOT-ring permutation fused into the store:
#pragma unroll
            for (int k = 0; k < 32; ++k) {
                unsigned ic  = ((unsigned)(k & 3) << 1) | ((unsigned)(k >> 2) << 11);
                unsigned sc0 = ssf(Pfold(ic));              // compile-time const
                unsigned sc1 = ssf(Pfold(ic) ^ 0x2001u);    // compile-time const
                unsigned a0 = spbC ^ sc0;
                unsigned a1 = spbC ^ sc1;
                float r0, r1, i0, i1;
                upk2(Rr[k], r0, r1);
                upk2(Ri[k], i0, i1);
                sre[a0] = r0;  sim[a0] = i0;
                sre[a1] = r1;  sim[a1] = i1;
            }
            __syncthreads();                 // scatter -> next pass A is cross-warp
        }
    }

    // ---------------- reduction: only 5 distinct sign-characters ---------------
    // sign of qubit q at (k,b0): bit(13-q) of [pbC ^ gmsk ^ Pfold(ic(k)) ^ b0*P(e0)]
    // k-dependence is linear over GF(2)^5; k bits -> i bits {1,2,11,12,13} with
    //   P(e1)=0x2003 P(e2)=0x2007 P(e11)=0x2FFF P(e12)=0x3FFF P(e13)=0x1FFF
    // -> per-qubit k-masks: q0->15 ; q1->24 ; q2..q10->28 ; q11->30 ; q12,13->31
    // pack halves combine with '-' exactly for q=0,13 (bits 13,0 of P(e0)=0x2001)
    // (validated at rel_err ~5.0e-6 in rounds 9-11 and 14 on this same geometry)
    {
        const unsigned M = gmsk;             // uniform (written pre-main-loop)
        const u64 PP = pk2( 1.0f,  1.0f);
        const u64 MM = pk2(-1.0f, -1.0f);
        u64 acc[5];
#pragma unroll
        for (int c = 0; c < 5; ++c) acc[c] = pk2(0.0f, 0.0f);

#pragma unroll
        for (int k = 0; k < 32; ++k) {
            u64 pr2 = fma2(Rr[k], Rr[k], mul2(Ri[k], Ri[k]));  // (|a0|^2,|a1|^2)
            acc[0] = fma2((__popc(k & 15) & 1) ? MM : PP, pr2, acc[0]);
            acc[1] = fma2((__popc(k & 24) & 1) ? MM : PP, pr2, acc[1]);
            acc[2] = fma2((__popc(k & 28) & 1) ? MM : PP, pr2, acc[2]);
            acc[3] = fma2((__popc(k & 30) & 1) ? MM : PP, pr2, acc[3]);
            acc[4] = fma2((__popc(k & 31) & 1) ? MM : PP, pr2, acc[4]);
        }
        float W0[5], W1[5];
#pragma unroll
        for (int c = 0; c < 5; ++c) upk2(acc[c], W0[c], W1[c]);

        float vq[NQ];
        vq[0]  = W0[0] - W1[0];
        vq[1]  = W0[1] + W1[1];
        const float vC = W0[2] + W1[2];
#pragma unroll
        for (int q = 2; q <= 10; ++q) vq[q] = vC;
        vq[11] = W0[3] + W1[3];
        vq[12] = W0[4] + W1[4];
        vq[13] = W0[4] - W1[4];

        const unsigned sgn = pbC ^ M;        // thread part + deferred-X part
#pragma unroll
        for (int q = 0; q < NQ; ++q) {
            float v = ((sgn >> (13 - q)) & 1u) ? -vq[q] : vq[q];
#pragma unroll
            for (int off = 16; off; off >>= 1)
                v += __shfl_xor_sync(0xffffffffu, v, off);
            if (lane == 0) atomicAdd(&red[q], v);
        }
    }
    __syncthreads();
    if (t < NQ)
        out[b * NQ + t] = red[t] * gG2;      // undo all deferred gate scales
}

extern "C" void kernel_launch(void* const* d_in, const int* in_sizes, int n_in,
                              void* d_out, int out_size)
{
    const float* x      = (const float*)d_in[0];
    const float* params = (const float*)d_in[1];
    if (n_in >= 2 && in_sizes[0] == NL * NQ) {   // defensive order check
        const float* tmp = x; x = params; params = tmp;
    }
    float* out = (float*)d_out;

    cudaFuncSetAttribute(qlayer_kernel,
                         cudaFuncAttributeMaxDynamicSharedMemorySize,
                         2 * DIM * (int)sizeof(float));
    qlayer_kernel<<<512, NTHR, 2 * DIM * sizeof(float)>>>(x, params, out);
}

// round 16
// speedup vs baseline: 1.1529x; 1.1529x over previous
#include <cuda_runtime.h>

typedef unsigned long long u64;

#define NQ     14
#define DIM    16384
#define NL     6
#define NG     (NL * NQ)
#define NTHR   256

// ---------------- packed f32x2 helpers (PTX-only on sm_103a) ----------------
__device__ __forceinline__ u64 pk2(float x, float y) {
    u64 r; asm("mov.b64 %0,{%1,%2};" : "=l"(r) : "f"(x), "f"(y)); return r;
}
__device__ __forceinline__ void upk2(u64 v, float& x, float& y) {
    asm("mov.b64 {%0,%1},%2;" : "=f"(x), "=f"(y) : "l"(v));
}
__device__ __forceinline__ u64 mul2(u64 a, u64 b) {
    u64 r; asm("mul.rn.f32x2 %0,%1,%2;" : "=l"(r) : "l"(a), "l"(b)); return r;
}
__device__ __forceinline__ u64 fma2(u64 a, u64 b, u64 c) {
    u64 r; asm("fma.rn.f32x2 %0,%1,%2,%3;" : "=l"(r) : "l"(a), "l"(b), "l"(c)); return r;
}
__device__ __forceinline__ u64 swap2(u64 a) {
    u64 r;
    asm("{\n\t.reg .f32 x,y;\n\tmov.b64 {x,y},%1;\n\tmov.b64 %0,{y,x};\n\t}"
        : "=l"(r) : "l"(a));
    return r;
}

// CNOT-ring permutation (GF(2)-linear): bits 0..12 = suffix-XOR, bit13 = XOR(0..12)
__device__ __forceinline__ unsigned Pfold(unsigned i) {
    unsigned z = i ^ (i >> 1);
    z ^= z >> 2; z ^= z >> 4; z ^= z >> 8;
    return (z & 0x1FFFu) | (((z ^ (i >> 13)) & 1u) << 13);
}
// float-word swizzle: XOR bits 1-5 with bits 6-10 (keeps bit0 -> u64 pairs intact)
__device__ __forceinline__ unsigned ssf(unsigned w) {
    return w ^ (((w >> 6) & 31u) << 1);
}

// Branch-free tan-form RX gate (always form A), state imag stored NEGATED:
//   r' = r - tau*i~p ; i~' = i~ + tau*rp    (4 fma2 per pair-op)
#define GATE_T(RM, T2, NT2)                                                 \
    _Pragma("unroll")                                                       \
    for (int k = 0; k < 32; ++k) {                                          \
        if (!(k & (RM))) {                                                  \
            const int k1 = k | (RM);                                        \
            u64 i0 = Ri[k], i1 = Ri[k1];                                    \
            Ri[k]  = fma2((T2),  Rr[k1], i0);                               \
            Ri[k1] = fma2((T2),  Rr[k],  i1);                               \
            Rr[k]  = fma2((NT2), i1, Rr[k]);                                \
            Rr[k1] = fma2((NT2), i0, Rr[k1]);                               \
        }                                                                   \
    }

__global__ void __launch_bounds__(NTHR, 1)
qlayer_kernel(const float* __restrict__ x,
              const float* __restrict__ params,
              float* __restrict__ out)
{
    extern __shared__ __align__(16) float sm[];
    float* sre = sm;            // DIM floats (real)
    float* sim = sm + DIM;      // DIM floats (negated imag)
    u64*   dre = (u64*)sre;     // packed pairs on i-bit0
    u64*   dim_ = (u64*)sim;

    __shared__ float gtau[NG];      // per-gate signed tau (layers 1..5 only)
    __shared__ float gdef[NG];      // per-gate deferred scalar (layers 1..5 only)
    __shared__ unsigned gmsk;       // accumulated deferred-X mask
    __shared__ float gG2;           // squared product of deferred scalars
    __shared__ float red[NQ];

    const int b = blockIdx.x;
    const int t = threadIdx.x;      // 8 bits
    const int lane = t & 31;
    const int hiB  = t >> 5;        // 3 bits (warp id) = i bits 11-13 in passes A/B
    const int midB = t & 31;

    if (t == 0) gmsk = 0u;
    if (t < NQ) red[t] = 0.0f;
    __syncthreads();                // gmsk=0 visible before atomicXor below

    // tan-form precompute for LAYERS 1..5 ONLY (layer 0 folds into the init:
    // RX(w0)RX(x) = RX(x+w0), same axis -> angle addition, exact).
    // form B (|s|>|c|): gate = s * (-iX) * (I + (-c/s) J); the (-iX) defers to a
    // final XOR mask, transformed by P once per remaining layer (incl. virtual last).
    if (t >= NQ && t < NG) {
        float h = 0.5f * params[t];
        float c = cosf(h), s = sinf(h);
        int fb = fabsf(s) > fabsf(c);
        gtau[t] = fb ? (-c / s) : (s / c);
        gdef[t] = fb ? s : c;
        if (fb) {
            const int l = t / NQ;
            const int q = t - l * NQ;
            unsigned m = 1u << (13 - q);       // i-bit of qubit q
            for (int n = 0; n < NL - l; ++n) m = Pfold(m);
            atomicXor(&gmsk, m);
        }
    }

    // ------- init product state (layer-0 RX folded in via angle addition) -------
    // pass-A layout: i = (t<<6) | (k<<1) | b0 ; bit bb of i <-> qubit (13-bb)
    // amp(i) = m(i) * (-i)^popcount(i) ; stored imag is NEGATED
    u64 Rr[32], Ri[32];
    {
        float cx[NQ], sx[NQ];
#pragma unroll
        for (int q = 0; q < NQ; ++q) {
            float h = 0.5f * (x[b * NQ + q] + params[q]);   // + layer-0 angle
            cx[q] = cosf(h);
            sx[q] = sinf(h);
        }
        float hm = 1.0f;                    // t bit kk -> i bit 6+kk -> qubit 7-kk
#pragma unroll
        for (int kk = 0; kk < 8; ++kk)
            hm *= ((t >> kk) & 1) ? sx[7 - kk] : cx[7 - kk];
        const int hp = __popc((unsigned)t) & 3;
        const float wr = (hp == 0) ? 1.0f : ((hp == 2) ? -1.0f : 0.0f);
        const float wi = (hp == 3) ? 1.0f : ((hp == 1) ? -1.0f : 0.0f);
#pragma unroll
        for (int k = 0; k < 32; ++k) {
            float m5 = hm;                  // j = 2k ; j bit mm -> qubit 13-mm
#pragma unroll
            for (int mm = 1; mm < 6; ++mm)
                m5 *= (((2 * k) >> mm) & 1) ? sx[13 - mm] : cx[13 - mm];
            float m0 = m5 * cx[13];         // b0 = 0
            float m1 = m5 * sx[13];         // b0 = 1
            const int ck = __popc((unsigned)k) & 3;   // compile-time per k
            float wkr, wki;
            if      (ck == 0) { wkr =  wr; wki =  wi; }
            else if (ck == 1) { wkr =  wi; wki = -wr; }
            else if (ck == 2) { wkr = -wr; wki = -wi; }
            else              { wkr = -wi; wki =  wr; }
            // amp0 = m0*w ; amp1 = m1*w*(-i) ; store NEGATED imag
            Rr[k] = pk2( m0 * wkr,  m1 * wki);
            Ri[k] = pk2(-m0 * wki,  m1 * wkr);
        }
    }

    // layer-0 CNOT-ring permutation: scatter init state through P from A-layout.
    // addr = ssf(P(i)) = ssf(P(t<<6)) ^ ssf(P(k<<1)) ^ b0*ssf(P(e0)) ;
    // ssf(P(e0)) = ssf(0x2001) = 0x2001 (bits 6-10 of 0x2001 are 0).
    {
        const unsigned sA = ssf(Pfold((unsigned)t << 6));
#pragma unroll
        for (int k = 0; k < 32; ++k) {
            unsigned c0 = ssf(Pfold((unsigned)k << 1));   // compile-time const
            unsigned a0 = sA ^ c0;
            unsigned a1 = a0 ^ 0x2001u;
            float r0, r1, i0v, i1v;
            upk2(Rr[k], r0, r1);
            upk2(Ri[k], i0v, i1v);
            sre[a0] = r0;  sim[a0] = i0v;
            sre[a1] = r1;  sim[a1] = i1v;
        }
    }
    __syncthreads();                // scatter + gtau/gdef visible to all

    // pass-C thread base (i bits from lane/hiB): lane bits at i{3,4,6,7,10},
    // warp bits at i{5,8,9} -- verified conflict-free geometry
    const unsigned Cbase =
        ((unsigned)(lane & 1)        << 3)  |
        ((unsigned)((lane >> 1) & 1) << 4)  |
        ((unsigned)(hiB & 1)         << 5)  |
        ((unsigned)((lane >> 2) & 1) << 6)  |
        ((unsigned)((lane >> 3) & 1) << 7)  |
        ((unsigned)((hiB >> 1) & 1)  << 8)  |
        ((unsigned)((hiB >> 2) & 1)  << 9)  |
        ((unsigned)((lane >> 4) & 1) << 10);
    const unsigned hi5C   = (Cbase >> 6) & 31u;
    const unsigned dbaseC = (Cbase >> 1) ^ hi5C;   // u64-index base for pass C
    const unsigned pbC    = Pfold(Cbase);
    const unsigned spbC   = ssf(pbC);              // float-word store base (pass C)

#pragma unroll 1
    for (int l = 1; l < NL; ++l) {           // layers 1..5 (layer 0 folded above)
        const float* lt = gtau + l * NQ;

        // ===== pass A : i = (t<<6)|(k<<1)|b0 ; gates on i bits 0..5 =====
#pragma unroll
        for (int k = 0; k < 32; ++k) {
            int du = t * 32 + (k ^ lane);
            Rr[k] = dre[du];
            Ri[k] = dim_[du];
        }
        {   // gate on i bit0 (qubit 13): pack bit -> half swaps, tan form
            float tu = lt[13];
            u64 t2 = pk2(tu, tu), nt2 = pk2(-tu, -tu);
#pragma unroll
            for (int k = 0; k < 32; ++k) {
                u64 rs = swap2(Rr[k]);
                u64 is = swap2(Ri[k]);
                Rr[k] = fma2(nt2, is, Rr[k]);
                Ri[k] = fma2(t2,  rs, Ri[k]);
            }
        }
#pragma unroll
        for (int m = 1; m < 6; ++m) {        // i bit m -> qubit 13-m
            float tu = lt[13 - m];
            u64 t2 = pk2(tu, tu), nt2 = pk2(-tu, -tu);
            GATE_T(1 << (m - 1), t2, nt2)
        }
#pragma unroll
        for (int k = 0; k < 32; ++k) {
            int du = t * 32 + (k ^ lane);
            dre[du] = Rr[k];
            dim_[du] = Ri[k];
        }
        // A->B exchange is warp-local (d bits 10-12 = warp id on both sides):
        // warp-level sync suffices and lets warps' L1/FMA phases overlap.
        __syncwarp();

        // ===== pass B : u64 idx = (hiB<<10)|(k<<5)|(midB^k) ; gates on i bits 6..10
#pragma unroll
        for (int k = 0; k < 32; ++k) {
            int du = (hiB << 10) | (k << 5) | (midB ^ k);
            Rr[k] = dre[du];
            Ri[k] = dim_[du];
        }
#pragma unroll
        for (int m = 0; m < 5; ++m) {        // i bit 6+m -> qubit 7-m
            float tu = lt[7 - m];
            u64 t2 = pk2(tu, tu), nt2 = pk2(-tu, -tu);
            GATE_T(1 << m, t2, nt2)
        }
#pragma unroll
        for (int k = 0; k < 32; ++k) {
            int du = (hiB << 10) | (k << 5) | (midB ^ k);
            dre[du] = Rr[k];
            dim_[du] = Ri[k];
        }
        __syncthreads();                     // B -> C is cross-warp

        // ===== pass C : k bits{0,1}->i{1,2}, k bits{2,3,4}->i{11,12,13} =====
#pragma unroll
        for (int k = 0; k < 32; ++k) {
            unsigned du = dbaseC ^ ((unsigned)(k & 3) | ((unsigned)(k >> 2) << 10));
            Rr[k] = dre[du];
            Ri[k] = dim_[du];
        }
        if (l < NL - 1)
            __syncthreads();                 // all gathers done before any scatter;
                                             // gates below overlap stragglers
#pragma unroll
        for (int m = 0; m < 3; ++m) {        // i bit 11+m -> qubit 2-m
            float tu = lt[2 - m];
            u64 t2 = pk2(tu, tu), nt2 = pk2(-tu, -tu);
            GATE_T(1 << (2 + m), t2, nt2)
        }

        if (l < NL - 1) {
            // CNOT-ring permutation fused into the store:
#pragma unroll
            for (int k = 0; k < 32; ++k) {
                unsigned ic  = ((unsigned)(k & 3) << 1) | ((unsigned)(k >> 2) << 11);
                unsigned sc0 = ssf(Pfold(ic));              // compile-time const
                unsigned sc1 = ssf(Pfold(ic) ^ 0x2001u);    // compile-time const
                unsigned a0 = spbC ^ sc0;
                unsigned a1 = spbC ^ sc1;
                float r0, r1, i0, i1;
                upk2(Rr[k], r0, r1);
                upk2(Ri[k], i0, i1);
                sre[a0] = r0;  sim[a0] = i0;
                sre[a1] = r1;  sim[a1] = i1;
            }
            __syncthreads();                 // scatter -> next pass A is cross-warp
        }
    }

    // squared global deferred scale over gates NQ..NG-1 (70 values), warp-parallel
    if (t < 32) {
        float p = gdef[NQ + t] * gdef[NQ + 32 + t];
        if (t < NG - NQ - 64) p *= gdef[NQ + 64 + t];       // t < 6
#pragma unroll
        for (int off = 16; off; off >>= 1)
            p *= __shfl_xor_sync(0xffffffffu, p, off);
        if (t == 0) gG2 = p * p;
    }

    // ---------------- reduction: only 5 distinct sign-characters ---------------
    // sign of qubit q at (k,b0): bit(13-q) of [pbC ^ gmsk ^ Pfold(ic(k)) ^ b0*P(e0)]
    // k-dependence is linear over GF(2)^5; k bits -> i bits {1,2,11,12,13} with
    //   P(e1)=0x2003 P(e2)=0x2007 P(e11)=0x2FFF P(e12)=0x3FFF P(e13)=0x1FFF
    // -> per-qubit k-masks: q0->15 ; q1->24 ; q2..q10->28 ; q11->30 ; q12,13->31
    // pack halves combine with '-' exactly for q=0,13 (bits 13,0 of P(e0)=0x2001)
    {
        const unsigned M = gmsk;             // uniform (written pre-main-loop)
        const u64 PP = pk2( 1.0f,  1.0f);
        const u64 MM = pk2(-1.0f, -1.0f);
        u64 acc[5];
#pragma unroll
        for (int c = 0; c < 5; ++c) acc[c] = pk2(0.0f, 0.0f);

#pragma unroll
        for (int k = 0; k < 32; ++k) {
            u64 pr2 = fma2(Rr[k], Rr[k], mul2(Ri[k], Ri[k]));  // (|a0|^2,|a1|^2)
            acc[0] = fma2((__popc(k & 15) & 1) ? MM : PP, pr2, acc[0]);
            acc[1] = fma2((__popc(k & 24) & 1) ? MM : PP, pr2, acc[1]);
            acc[2] = fma2((__popc(k & 28) & 1) ? MM : PP, pr2, acc[2]);
            acc[3] = fma2((__popc(k & 30) & 1) ? MM : PP, pr2, acc[3]);
            acc[4] = fma2((__popc(k & 31) & 1) ? MM : PP, pr2, acc[4]);
        }
        float W0[5], W1[5];
#pragma unroll
        for (int c = 0; c < 5; ++c) upk2(acc[c], W0[c], W1[c]);

        float vq[NQ];
        vq[0]  = W0[0] - W1[0];
        vq[1]  = W0[1] + W1[1];
        const float vC = W0[2] + W1[2];
#pragma unroll
        for (int q = 2; q <= 10; ++q) vq[q] = vC;
        vq[11] = W0[3] + W1[3];
        vq[12] = W0[4] + W1[4];
        vq[13] = W0[4] - W1[4];

        const unsigned sgn = pbC ^ M;        // thread part + deferred-X part
#pragma unroll
        for (int q = 0; q < NQ; ++q) {
            float v = ((sgn >> (13 - q)) & 1u) ? -vq[q] : vq[q];
#pragma unroll
            for (int off = 16; off; off >>= 1)
                v += __shfl_xor_sync(0xffffffffu, v, off);
            if (lane == 0) atomicAdd(&red[q], v);
        }
    }
    __syncthreads();
    if (t < NQ)
        out[b * NQ + t] = red[t] * gG2;      // undo all deferred gate scales
}

extern "C" void kernel_launch(void* const* d_in, const int* in_sizes, int n_in,
                              void* d_out, int out_size)
{
    const float* x      = (const float*)d_in[0];
    const float* params = (const float*)d_in[1];
    if (n_in >= 2 && in_sizes[0] == NL * NQ) {   // defensive order check
        const float* tmp = x; x = params; params = tmp;
    }
    float* out = (float*)d_out;

    cudaFuncSetAttribute(qlayer_kernel,
                         cudaFuncAttributeMaxDynamicSharedMemorySize,
                         2 * DIM * (int)sizeof(float));
    qlayer_kernel<<<512, NTHR, 2 * DIM * sizeof(float)>>>(x, params, out);
}

// round 17
// speedup vs baseline: 1.2222x; 1.0601x over previous
#include <cuda_runtime.h>

typedef unsigned long long u64;

#define NQ     14
#define DIM    16384
#define NL     6
#define NG     (NL * NQ)
#define NTHR   256

// ---------------- packed f32x2 helpers (PTX-only on sm_103a) ----------------
__device__ __forceinline__ u64 pk2(float x, float y) {
    u64 r; asm("mov.b64 %0,{%1,%2};" : "=l"(r) : "f"(x), "f"(y)); return r;
}
__device__ __forceinline__ void upk2(u64 v, float& x, float& y) {
    asm("mov.b64 {%0,%1},%2;" : "=f"(x), "=f"(y) : "l"(v));
}
__device__ __forceinline__ u64 mul2(u64 a, u64 b) {
    u64 r; asm("mul.rn.f32x2 %0,%1,%2;" : "=l"(r) : "l"(a), "l"(b)); return r;
}
__device__ __forceinline__ u64 fma2(u64 a, u64 b, u64 c) {
    u64 r; asm("fma.rn.f32x2 %0,%1,%2,%3;" : "=l"(r) : "l"(a), "l"(b), "l"(c)); return r;
}
__device__ __forceinline__ u64 swap2(u64 a) {
    u64 r;
    asm("{\n\t.reg .f32 x,y;\n\tmov.b64 {x,y},%1;\n\tmov.b64 %0,{y,x};\n\t}"
        : "=l"(r) : "l"(a));
    return r;
}

// CNOT-ring permutation (GF(2)-linear): bits 0..12 = suffix-XOR, bit13 = XOR(0..12)
__device__ __forceinline__ unsigned Pfold(unsigned i) {
    unsigned z = i ^ (i >> 1);
    z ^= z >> 2; z ^= z >> 4; z ^= z >> 8;
    return (z & 0x1FFFu) | (((z ^ (i >> 13)) & 1u) << 13);
}
// float-word swizzle: XOR bits 1-5 with bits 6-10 (keeps bit0 -> u64 pairs intact)
__device__ __forceinline__ unsigned ssf(unsigned w) {
    return w ^ (((w >> 6) & 31u) << 1);
}

// Branch-free tan-form RX gate (always form A), state imag stored NEGATED:
//   r' = r - tau*i~p ; i~' = i~ + tau*rp    (4 fma2 per pair-op)
#define GATE_T(RM, T2, NT2)                                                 \
    _Pragma("unroll")                                                       \
    for (int k = 0; k < 32; ++k) {                                          \
        if (!(k & (RM))) {                                                  \
            const int k1 = k | (RM);                                        \
            u64 i0 = Ri[k], i1 = Ri[k1];                                    \
            Ri[k]  = fma2((T2),  Rr[k1], i0);                               \
            Ri[k1] = fma2((T2),  Rr[k],  i1);                               \
            Rr[k]  = fma2((NT2), i1, Rr[k]);                                \
            Rr[k1] = fma2((NT2), i0, Rr[k1]);                               \
        }                                                                   \
    }

__global__ void __launch_bounds__(NTHR, 1)
qlayer_kernel(const float* __restrict__ x,
              const float* __restrict__ params,
              float* __restrict__ out)
{
    extern __shared__ __align__(16) float sm[];
    float* sre = sm;            // DIM floats (real)
    float* sim = sm + DIM;      // DIM floats (negated imag)
    u64*   dre = (u64*)sre;     // packed pairs on i-bit0
    u64*   dim_ = (u64*)sim;

    __shared__ float gtau[NG];      // per-gate signed tau (layers 1..5 only)
    __shared__ float gdef[NG];      // per-gate deferred scalar (layers 1..5 only)
    __shared__ unsigned gmsk;       // accumulated deferred-X mask
    __shared__ float gG2;           // squared product of deferred scalars
    __shared__ float red2[NQ][8];   // per-warp partial sums (no atomics)

    const int b = blockIdx.x;
    const int t = threadIdx.x;      // 8 bits
    const int lane = t & 31;
    const int hiB  = t >> 5;        // 3 bits (warp id) = i bits 11-13 in passes A/B
    const int midB = t & 31;

    // hoist GMEM x loads to kernel entry (latency overlaps precompute below)
    float xv[NQ];
#pragma unroll
    for (int q = 0; q < NQ; ++q) xv[q] = x[b * NQ + q];

    if (t == 0) gmsk = 0u;
    __syncthreads();                // gmsk=0 visible before atomicXor below

    // tan-form precompute for LAYERS 1..5 ONLY (layer 0 folds into the init:
    // RX(w0)RX(x) = RX(x+w0), same axis -> angle addition, exact).
    // form B (|s|>|c|): gate = s * (-iX) * (I + (-c/s) J); the (-iX) defers to a
    // final XOR mask, transformed by P once per remaining layer (incl. virtual last).
    if (t >= NQ && t < NG) {
        float h = 0.5f * params[t];
        float c = cosf(h), s = sinf(h);
        int fb = fabsf(s) > fabsf(c);
        gtau[t] = fb ? (-c / s) : (s / c);
        gdef[t] = fb ? s : c;
        if (fb) {
            const int l = t / NQ;
            const int q = t - l * NQ;
            unsigned m = 1u << (13 - q);       // i-bit of qubit q
            for (int n = 0; n < NL - l; ++n) m = Pfold(m);
            atomicXor(&gmsk, m);
        }
    }

    // ------- init product state (layer-0 RX folded in via angle addition) -------
    // pass-A layout: i = (t<<6) | (k<<1) | b0 ; bit bb of i <-> qubit (13-bb)
    // amp(i) = m(i) * (-i)^popcount(i) ; stored imag is NEGATED
    u64 Rr[32], Ri[32];
    {
        float cx[NQ], sx[NQ];
#pragma unroll
        for (int q = 0; q < NQ; ++q) {
            float h = 0.5f * (xv[q] + params[q]);   // + layer-0 angle
            cx[q] = cosf(h);
            sx[q] = sinf(h);
        }
        float hm = 1.0f;                    // t bit kk -> i bit 6+kk -> qubit 7-kk
#pragma unroll
        for (int kk = 0; kk < 8; ++kk)
            hm *= ((t >> kk) & 1) ? sx[7 - kk] : cx[7 - kk];
        const int hp = __popc((unsigned)t) & 3;
        const float wr = (hp == 0) ? 1.0f : ((hp == 2) ? -1.0f : 0.0f);
        const float wi = (hp == 3) ? 1.0f : ((hp == 1) ? -1.0f : 0.0f);
#pragma unroll
        for (int k = 0; k < 32; ++k) {
            float m5 = hm;                  // j = 2k ; j bit mm -> qubit 13-mm
#pragma unroll
            for (int mm = 1; mm < 6; ++mm)
                m5 *= (((2 * k) >> mm) & 1) ? sx[13 - mm] : cx[13 - mm];
            float m0 = m5 * cx[13];         // b0 = 0
            float m1 = m5 * sx[13];         // b0 = 1
            const int ck = __popc((unsigned)k) & 3;   // compile-time per k
            float wkr, wki;
            if      (ck == 0) { wkr =  wr; wki =  wi; }
            else if (ck == 1) { wkr =  wi; wki = -wr; }
            else if (ck == 2) { wkr = -wr; wki = -wi; }
            else              { wkr = -wi; wki =  wr; }
            // amp0 = m0*w ; amp1 = m1*w*(-i) ; store NEGATED imag
            Rr[k] = pk2( m0 * wkr,  m1 * wki);
            Ri[k] = pk2(-m0 * wki,  m1 * wkr);
        }
    }

    // layer-0 CNOT-ring permutation: scatter init state through P from A-layout.
    // addr = ssf(P(i)) = ssf(P(t<<6)) ^ ssf(P(k<<1)) ^ b0*ssf(P(e0)) ;
    // ssf(P(e0)) = ssf(0x2001) = 0x2001 (bits 6-10 of 0x2001 are 0).
    {
        const unsigned sA = ssf(Pfold((unsigned)t << 6));
#pragma unroll
        for (int k = 0; k < 32; ++k) {
            unsigned c0 = ssf(Pfold((unsigned)k << 1));   // compile-time const
            unsigned a0 = sA ^ c0;
            unsigned a1 = a0 ^ 0x2001u;
            float r0, r1, i0v, i1v;
            upk2(Rr[k], r0, r1);
            upk2(Ri[k], i0v, i1v);
            sre[a0] = r0;  sim[a0] = i0v;
            sre[a1] = r1;  sim[a1] = i1v;
        }
    }
    __syncthreads();                // scatter + gtau/gdef visible to all

    // pass-C thread base (i bits from lane/hiB): lane bits at i{3,4,6,7,10},
    // warp bits at i{5,8,9} -- verified conflict-free geometry
    const unsigned Cbase =
        ((unsigned)(lane & 1)        << 3)  |
        ((unsigned)((lane >> 1) & 1) << 4)  |
        ((unsigned)(hiB & 1)         << 5)  |
        ((unsigned)((lane >> 2) & 1) << 6)  |
        ((unsigned)((lane >> 3) & 1) << 7)  |
        ((unsigned)((hiB >> 1) & 1)  << 8)  |
        ((unsigned)((hiB >> 2) & 1)  << 9)  |
        ((unsigned)((lane >> 4) & 1) << 10);
    const unsigned hi5C   = (Cbase >> 6) & 31u;
    const unsigned dbaseC = (Cbase >> 1) ^ hi5C;   // u64-index base for pass C
    const unsigned pbC    = Pfold(Cbase);
    const unsigned spbC   = ssf(pbC);              // float-word store base (pass C)

#pragma unroll 1
    for (int l = 1; l < NL; ++l) {           // layers 1..5 (layer 0 folded above)
        const float* lt = gtau + l * NQ;

        // ===== pass A : i = (t<<6)|(k<<1)|b0 ; gates on i bits 0..5 =====
        // pack-bit gate (qubit 13, tan form, half swaps) FUSED into the load loop
        // so each arriving record feeds immediate FMA work (crossbar/FMA overlap).
        {
            float tu = lt[13];
            u64 t2 = pk2(tu, tu), nt2 = pk2(-tu, -tu);
#pragma unroll
            for (int k = 0; k < 32; ++k) {
                int du = t * 32 + (k ^ lane);
                u64 r = dre[du];
                u64 i = dim_[du];
                u64 rs = swap2(r);
                u64 is = swap2(i);
                Rr[k] = fma2(nt2, is, r);
                Ri[k] = fma2(t2,  rs, i);
            }
        }
#pragma unroll
        for (int m = 1; m < 6; ++m) {        // i bit m -> qubit 13-m
            float tu = lt[13 - m];
            u64 t2 = pk2(tu, tu), nt2 = pk2(-tu, -tu);
            GATE_T(1 << (m - 1), t2, nt2)
        }
#pragma unroll
        for (int k = 0; k < 32; ++k) {
            int du = t * 32 + (k ^ lane);
            dre[du] = Rr[k];
            dim_[du] = Ri[k];
        }
        // A->B exchange is warp-local (d bits 10-12 = warp id on both sides):
        // warp-level sync suffices and lets warps' L1/FMA phases overlap.
        __syncwarp();

        // ===== pass B : u64 idx = (hiB<<10)|(k<<5)|(midB^k) ; gates on i bits 6..10
        // first gate (i bit 6 = reg bit 0, pairs 2j/2j+1) FUSED into the load loop
        {
            float tu = lt[7];
            u64 t2 = pk2(tu, tu), nt2 = pk2(-tu, -tu);
#pragma unroll
            for (int kk = 0; kk < 16; ++kk) {
                const int k0 = 2 * kk, k1 = 2 * kk + 1;
                int d0 = (hiB << 10) | (k0 << 5) | (midB ^ k0);
                int d1 = (hiB << 10) | (k1 << 5) | (midB ^ k1);
                u64 r0 = dre[d0], i0 = dim_[d0];
                u64 r1 = dre[d1], i1 = dim_[d1];
                Ri[k0] = fma2(t2,  r1, i0);
                Ri[k1] = fma2(t2,  r0, i1);
                Rr[k0] = fma2(nt2, i1, r0);
                Rr[k1] = fma2(nt2, i0, r1);
            }
        }
#pragma unroll
        for (int m = 1; m < 5; ++m) {        // i bit 6+m -> qubit 7-m
            float tu = lt[7 - m];
            u64 t2 = pk2(tu, tu), nt2 = pk2(-tu, -tu);
            GATE_T(1 << m, t2, nt2)
        }
#pragma unroll
        for (int k = 0; k < 32; ++k) {
            int du = (hiB << 10) | (k << 5) | (midB ^ k);
            dre[du] = Rr[k];
            dim_[du] = Ri[k];
        }
        __syncthreads();                     // B -> C is cross-warp

        // ===== pass C : k bits{0,1}->i{1,2}, k bits{2,3,4}->i{11,12,13} =====
#pragma unroll
        for (int k = 0; k < 32; ++k) {
            unsigned du = dbaseC ^ ((unsigned)(k & 3) | ((unsigned)(k >> 2) << 10));
            Rr[k] = dre[du];
            Ri[k] = dim_[du];
        }
        if (l < NL - 1)
            __syncthreads();                 // all gathers done before any scatter;
                                             // gates below overlap stragglers
#pragma unroll
        for (int m = 0; m < 3; ++m) {        // i bit 11+m -> qubit 2-m
            float tu = lt[2 - m];
            u64 t2 = pk2(tu, tu), nt2 = pk2(-tu, -tu);
            GATE_T(1 << (2 + m), t2, nt2)
        }

        if (l < NL - 1) {
            // CNOT-ring permutation fused into the store:
#pragma unroll
            for (int k = 0; k < 32; ++k) {
                unsigned ic  = ((unsigned)(k & 3) << 1) | ((unsigned)(k >> 2) << 11);
                unsigned sc0 = ssf(Pfold(ic));              // compile-time const
                unsigned sc1 = ssf(Pfold(ic) ^ 0x2001u);    // compile-time const
                unsigned a0 = spbC ^ sc0;
                unsigned a1 = spbC ^ sc1;
                float r0, r1, i0, i1;
                upk2(Rr[k], r0, r1);
                upk2(Ri[k], i0, i1);
                sre[a0] = r0;  sim[a0] = i0;
                sre[a1] = r1;  sim[a1] = i1;
            }
            __syncthreads();                 // scatter -> next pass A is cross-warp
        }
    }

    // squared global deferred scale over gates NQ..NG-1 (70 values), warp-parallel
    if (t < 32) {
        float p = gdef[NQ + t] * gdef[NQ + 32 + t];
        if (t < NG - NQ - 64) p *= gdef[NQ + 64 + t];       // t < 6
#pragma unroll
        for (int off = 16; off; off >>= 1)
            p *= __shfl_xor_sync(0xffffffffu, p, off);
        if (t == 0) gG2 = p * p;
    }

    // ---------------- reduction: only 5 distinct sign-characters ---------------
    // sign of qubit q at (k,b0): bit(13-q) of [pbC ^ gmsk ^ Pfold(ic(k)) ^ b0*P(e0)]
    // k-dependence is linear over GF(2)^5; k bits -> i bits {1,2,11,12,13} with
    //   P(e1)=0x2003 P(e2)=0x2007 P(e11)=0x2FFF P(e12)=0x3FFF P(e13)=0x1FFF
    // -> per-qubit k-masks: q0->15 ; q1->24 ; q2..q10->28 ; q11->30 ; q12,13->31
    // pack halves combine with '-' exactly for q=0,13 (bits 13,0 of P(e0)=0x2001)
    {
        const unsigned M = gmsk;             // uniform (written pre-main-loop)
        const u64 PP = pk2( 1.0f,  1.0f);
        const u64 MM = pk2(-1.0f, -1.0f);
        u64 acc[5];
#pragma unroll
        for (int c = 0; c < 5; ++c) acc[c] = pk2(0.0f, 0.0f);

#pragma unroll
        for (int k = 0; k < 32; ++k) {
            u64 pr2 = fma2(Rr[k], Rr[k], mul2(Ri[k], Ri[k]));  // (|a0|^2,|a1|^2)
            acc[0] = fma2((__popc(k & 15) & 1) ? MM : PP, pr2, acc[0]);
            acc[1] = fma2((__popc(k & 24) & 1) ? MM : PP, pr2, acc[1]);
            acc[2] = fma2((__popc(k & 28) & 1) ? MM : PP, pr2, acc[2]);
            acc[3] = fma2((__popc(k & 30) & 1) ? MM : PP, pr2, acc[3]);
            acc[4] = fma2((__popc(k & 31) & 1) ? MM : PP, pr2, acc[4]);
        }
        float W0[5], W1[5];
#pragma unroll
        for (int c = 0; c < 5; ++c) upk2(acc[c], W0[c], W1[c]);

        float vq[NQ];
        vq[0]  = W0[0] - W1[0];
        vq[1]  = W0[1] + W1[1];
        const float vC = W0[2] + W1[2];
#pragma unroll
        for (int q = 2; q <= 10; ++q) vq[q] = vC;
        vq[11] = W0[3] + W1[3];
        vq[12] = W0[4] + W1[4];
        vq[13] = W0[4] - W1[4];

        const unsigned sgn = pbC ^ M;        // thread part + deferred-X part
#pragma unroll
        for (int q = 0; q < NQ; ++q) {
            float v = ((sgn >> (13 - q)) & 1u) ? -vq[q] : vq[q];
#pragma unroll
            for (int off = 16; off; off >>= 1)
                v += __shfl_xor_sync(0xffffffffu, v, off);
            if (lane == 0) red2[q][hiB] = v;   // per-warp slot: no atomics
        }
    }
    __syncthreads();
    if (t < NQ) {
        float s = 0.0f;
#pragma unroll
        for (int w = 0; w < 8; ++w) s += red2[t][w];
        out[b * NQ + t] = s * gG2;           // undo all deferred gate scales
    }
}

extern "C" void kernel_launch(void* const* d_in, const int* in_sizes, int n_in,
                              void* d_out, int out_size)
{
    const float* x      = (const float*)d_in[0];
    const float* params = (const float*)d_in[1];
    if (n_in >= 2 && in_sizes[0] == NL * NQ) {   // defensive order check
        const float* tmp = x; x = params; params = tmp;
    }
    float* out = (float*)d_out;

    cudaFuncSetAttribute(qlayer_kernel,
                         cudaFuncAttributeMaxDynamicSharedMemorySize,
                         2 * DIM * (int)sizeof(float));
    qlayer_kernel<<<512, NTHR, 2 * DIM * sizeof(float)>>>(x, params, out);
}